// round 1
// baseline (speedup 1.0000x reference)
#include <cuda_runtime.h>
#include <math.h>

#define BATCH 4
#define DIM 384
#define HEADS 8
#define CH 48            // DIM/HEADS
#define HW 16384         // 128*128
#define C3 1152          // 3*DIM
#define EPS 1e-12f
#define CLAMPV 50.0f
#define NCHUNKS 16       // n-chunks for attn S partials

// ---------------- device scratch (no allocation allowed) ----------------
__device__ float g_t0[BATCH * C3 * HW];        // qkv GEMM output   (~302 MB)
__device__ float g_t1[BATCH * C3 * HW];        // depthwise output  (~302 MB)
__device__ float g_attn_out[BATCH * DIM * HW]; // attention output  (~100 MB)
__device__ float g_sigma[4];                   // σ_qkv, σ_dw, σ_proj, combined scale
__device__ float g_invnorm[BATCH * 2 * DIM];   // inv L2 norms of q (0..383) and k (384..767)
__device__ float g_Spart[NCHUNKS * BATCH * HEADS * CH * CH]; // partial logits
__device__ float g_S[BATCH * HEADS * CH * CH];               // softmaxed attn

// ---------------- spectral sigma: sigma = || wm @ unit(wm^T u) || ----------------
__global__ void sigma_kernel(const float* __restrict__ qkvw,
                             const float* __restrict__ dww,
                             const float* __restrict__ projw,
                             const float* __restrict__ uq,
                             const float* __restrict__ ud,
                             const float* __restrict__ up)
{
    int which = blockIdx.x;
    const float* wm; const float* u; int h, w;
    if (which == 0)      { wm = qkvw;  u = uq; h = C3;  w = DIM; }
    else if (which == 1) { wm = dww;   u = ud; h = C3;  w = 9;   }
    else                 { wm = projw; u = up; h = DIM; w = DIM; }

    __shared__ float v[DIM];
    __shared__ float red[256];
    int tid = threadIdx.x;

    // v = wm^T u
    for (int j = tid; j < w; j += 256) {
        float s = 0.f;
        for (int i = 0; i < h; i++) s += wm[i * w + j] * u[i];
        v[j] = s;
    }
    __syncthreads();

    float ss = 0.f;
    for (int j = tid; j < w; j += 256) ss += v[j] * v[j];
    red[tid] = ss; __syncthreads();
    for (int s = 128; s > 0; s >>= 1) { if (tid < s) red[tid] += red[tid + s]; __syncthreads(); }
    float vinv = 1.f / fmaxf(sqrtf(red[0]), EPS);
    __syncthreads();
    for (int j = tid; j < w; j += 256) v[j] *= vinv;
    __syncthreads();

    // wv = wm v ; sigma = ||wv||^2 / max(||wv||, eps)
    float ss2 = 0.f;
    for (int i = tid; i < h; i += 256) {
        float s = 0.f;
        for (int j = 0; j < w; j++) s += wm[i * w + j] * v[j];
        ss2 += s * s;
    }
    red[tid] = ss2; __syncthreads();
    for (int s = 128; s > 0; s >>= 1) { if (tid < s) red[tid] += red[tid + s]; __syncthreads(); }
    if (tid == 0) {
        float sq = red[0];
        g_sigma[which] = sq / fmaxf(sqrtf(sq), EPS);
    }
}

__global__ void scale_kernel()
{
    if (threadIdx.x == 0) {
        float s = 1.f;
        s /= (g_sigma[0] + EPS);
        s /= (g_sigma[1] + EPS);
        s /= (g_sigma[2] + EPS);
        g_sigma[3] = s;
    }
}

// ---------------- SGEMM: C[b][m][n] = sum_k A[m][k] * B[b][k][n] ----------------
// 128x128x16 tile, 256 threads, 8x8 per thread, float4 everywhere.
// M % 128 == 0, N % 128 == 0, K % 16 == 0 guaranteed by problem shapes.
__global__ __launch_bounds__(256)
void sgemm128(const float* __restrict__ A, const float* __restrict__ B,
              float* __restrict__ C, int M, int N, int K,
              long strideB, long strideC, int useScale)
{
    const float* Bb = B + (long)blockIdx.z * strideB;
    float* Cb = C + (long)blockIdx.z * strideC;

    __shared__ float As[16][128];
    __shared__ float Bs[16][128];

    int tid = threadIdx.x;
    int bm = blockIdx.y, bn = blockIdx.x;
    int ty = tid >> 4, tx = tid & 15;

    float acc[8][8];
#pragma unroll
    for (int i = 0; i < 8; i++)
#pragma unroll
        for (int j = 0; j < 8; j++) acc[i][j] = 0.f;

    for (int kt = 0; kt < K; kt += 16) {
#pragma unroll
        for (int i = 0; i < 2; i++) {
            int idx = tid + i * 256;
            int row = idx >> 2; int k4 = (idx & 3) << 2;
            float4 a4 = *(const float4*)&A[(bm * 128 + row) * K + kt + k4];
            As[k4 + 0][row] = a4.x; As[k4 + 1][row] = a4.y;
            As[k4 + 2][row] = a4.z; As[k4 + 3][row] = a4.w;
        }
#pragma unroll
        for (int i = 0; i < 2; i++) {
            int idx = tid + i * 256;
            int row = idx >> 5; int n4 = (idx & 31) << 2;
            *(float4*)&Bs[row][n4] =
                *(const float4*)&Bb[(long)(kt + row) * N + bn * 128 + n4];
        }
        __syncthreads();

#pragma unroll
        for (int kk = 0; kk < 16; kk++) {
            float4 a0 = *(const float4*)&As[kk][ty * 8];
            float4 a1 = *(const float4*)&As[kk][ty * 8 + 4];
            float4 b0 = *(const float4*)&Bs[kk][tx * 8];
            float4 b1 = *(const float4*)&Bs[kk][tx * 8 + 4];
            float a[8] = {a0.x, a0.y, a0.z, a0.w, a1.x, a1.y, a1.z, a1.w};
            float b[8] = {b0.x, b0.y, b0.z, b0.w, b1.x, b1.y, b1.z, b1.w};
#pragma unroll
            for (int i = 0; i < 8; i++)
#pragma unroll
                for (int j = 0; j < 8; j++)
                    acc[i][j] = fmaf(a[i], b[j], acc[i][j]);
        }
        __syncthreads();
    }

    float sc = useScale ? g_sigma[3] : 1.0f;
#pragma unroll
    for (int i = 0; i < 8; i++) {
        long row = bm * 128 + ty * 8 + i;
#pragma unroll
        for (int j = 0; j < 8; j += 4) {
            float4 o;
            o.x = acc[i][j] * sc; o.y = acc[i][j + 1] * sc;
            o.z = acc[i][j + 2] * sc; o.w = acc[i][j + 3] * sc;
            *(float4*)&Cb[row * N + bn * 128 + tx * 8 + j] = o;
        }
    }
}

// ---------------- 3x3 depthwise conv, pad=1 (raw weights) ----------------
// grid (16, 1152, 4) : 8 output rows per block, 128 threads (one per x)
__global__ __launch_bounds__(128)
void dwconv(const float* __restrict__ in, const float* __restrict__ w,
            float* __restrict__ out)
{
    int ych = blockIdx.x * 8;
    int ch = blockIdx.y;
    int b = blockIdx.z;
    const float* ip = in + (((long)b * C3 + ch) << 14);
    float* op = out + (((long)b * C3 + ch) << 14);

    __shared__ float rows[10][130];
    int x = threadIdx.x;
#pragma unroll
    for (int r = 0; r < 10; r++) {
        int yy = ych + r - 1;
        rows[r][x + 1] = (yy >= 0 && yy < 128) ? ip[(yy << 7) + x] : 0.f;
        if (x == 0) { rows[r][0] = 0.f; rows[r][129] = 0.f; }
    }
    float w00 = w[ch * 9 + 0], w01 = w[ch * 9 + 1], w02 = w[ch * 9 + 2];
    float w10 = w[ch * 9 + 3], w11 = w[ch * 9 + 4], w12 = w[ch * 9 + 5];
    float w20 = w[ch * 9 + 6], w21 = w[ch * 9 + 7], w22 = w[ch * 9 + 8];
    __syncthreads();

#pragma unroll
    for (int yo = 0; yo < 8; yo++) {
        float s = rows[yo][x]     * w00 + rows[yo][x + 1]     * w01 + rows[yo][x + 2]     * w02
                + rows[yo + 1][x] * w10 + rows[yo + 1][x + 1] * w11 + rows[yo + 1][x + 2] * w12
                + rows[yo + 2][x] * w20 + rows[yo + 2][x + 1] * w21 + rows[yo + 2][x + 2] * w22;
        op[((ych + yo) << 7) + x] = s;
    }
}

// ---------------- per-(b, channel) inverse L2 norm over spatial dim ----------------
// grid 4*768 blocks; channel in [0,768): q is 0..383, k is 384..767 of g_t1
__global__ __launch_bounds__(256)
void norm_kernel(const float* __restrict__ t)
{
    int idx = blockIdx.x;
    int b = idx / (2 * DIM), c = idx % (2 * DIM);
    const float4* p = (const float4*)(t + (((long)b * C3 + c) << 14));
    float ss = 0.f;
    for (int i = threadIdx.x; i < HW / 4; i += 256) {
        float4 v = p[i];
        ss += v.x * v.x + v.y * v.y + v.z * v.z + v.w * v.w;
    }
    __shared__ float red[256];
    red[threadIdx.x] = ss; __syncthreads();
    for (int s = 128; s > 0; s >>= 1) {
        if (threadIdx.x < s) red[threadIdx.x] += red[threadIdx.x + s];
        __syncthreads();
    }
    if (threadIdx.x == 0) g_invnorm[idx] = 1.f / fmaxf(sqrtf(red[0]), EPS);
}

// ---------------- raw attention logits (partial over n-chunks) ----------------
// grid (NCHUNKS, 32); block 256 = 16x16, each thread a 3x3 micro tile of S
__global__ __launch_bounds__(256)
void attn_s(const float* __restrict__ t)
{
    int bh = blockIdx.y;
    int b = bh >> 3, head = bh & 7;
    int n0 = blockIdx.x * (HW / NCHUNKS);   // 1024
    const float* qp = t + ((((long)b * C3) + head * CH) << 14);
    const float* kp = t + ((((long)b * C3) + DIM + head * CH) << 14);

    __shared__ float qs[32][49];
    __shared__ float ks[32][49];
    int tid = threadIdx.x;
    int ty = tid >> 4, tx = tid & 15;
    float acc[3][3] = {};

    for (int nt = 0; nt < 32; nt++) {
        int nb = n0 + nt * 32;
        for (int i = tid; i < CH * 32; i += 256) {
            int c = i >> 5, nn = i & 31;
            qs[nn][c] = qp[(c << 14) + nb + nn];
            ks[nn][c] = kp[(c << 14) + nb + nn];
        }
        __syncthreads();
#pragma unroll
        for (int nn = 0; nn < 32; nn++) {
            float a0 = qs[nn][ty * 3], a1 = qs[nn][ty * 3 + 1], a2 = qs[nn][ty * 3 + 2];
            float b0 = ks[nn][tx * 3], b1 = ks[nn][tx * 3 + 1], b2 = ks[nn][tx * 3 + 2];
            acc[0][0] = fmaf(a0, b0, acc[0][0]); acc[0][1] = fmaf(a0, b1, acc[0][1]); acc[0][2] = fmaf(a0, b2, acc[0][2]);
            acc[1][0] = fmaf(a1, b0, acc[1][0]); acc[1][1] = fmaf(a1, b1, acc[1][1]); acc[1][2] = fmaf(a1, b2, acc[1][2]);
            acc[2][0] = fmaf(a2, b0, acc[2][0]); acc[2][1] = fmaf(a2, b1, acc[2][1]); acc[2][2] = fmaf(a2, b2, acc[2][2]);
        }
        __syncthreads();
    }

    float* Sp = g_Spart + ((long)blockIdx.x * 32 + bh) * (CH * CH);
#pragma unroll
    for (int i = 0; i < 3; i++)
#pragma unroll
        for (int j = 0; j < 3; j++)
            Sp[(ty * 3 + i) * CH + tx * 3 + j] = acc[i][j];
}

// ---------------- finalize: reduce partials, scale, clamp, softmax ----------------
// grid 32*48 blocks (one attn row each), block 64
__global__ __launch_bounds__(64)
void softmax_kernel(const float* __restrict__ temp)
{
    int blk = blockIdx.x;
    int bh = blk / CH, c = blk % CH;
    int b = bh >> 3, head = bh & 7;
    int d = threadIdx.x;
    __shared__ float sm[64];

    float myv = 0.f, val = -1e30f;
    if (d < CH) {
        float raw = 0.f;
#pragma unroll
        for (int ch = 0; ch < NCHUNKS; ch++)
            raw += g_Spart[((long)ch * 32 + bh) * (CH * CH) + c * CH + d];
        float invq = g_invnorm[b * 2 * DIM + head * CH + c];
        float invk = g_invnorm[b * 2 * DIM + DIM + head * CH + d];
        myv = raw * invq * invk * temp[head];
        myv = fminf(fmaxf(myv, -CLAMPV), CLAMPV);
        val = myv;
    }
    sm[d] = val; __syncthreads();
    for (int s = 32; s > 0; s >>= 1) { if (d < s) sm[d] = fmaxf(sm[d], sm[d + s]); __syncthreads(); }
    float m = sm[0]; __syncthreads();
    float e = (d < CH) ? expf(myv - m) : 0.f;
    sm[d] = e; __syncthreads();
    for (int s = 32; s > 0; s >>= 1) { if (d < s) sm[d] += sm[d + s]; __syncthreads(); }
    if (d < CH) g_S[(long)bh * (CH * CH) + c * CH + d] = e / sm[0];
}

// ---------------- out = attn @ v ----------------
// grid (32, 32): n-chunks of 512 x (b,head); 256 threads, 2 n per thread
__global__ __launch_bounds__(256)
void attn_o(const float* __restrict__ t, float* __restrict__ out)
{
    int bh = blockIdx.y;
    int b = bh >> 3, head = bh & 7;
    const float* vp = t + ((((long)b * C3) + 2 * DIM + head * CH) << 14);
    float* op = out + ((((long)b * DIM) + head * CH) << 14);

    __shared__ float Ss[CH * CH];
    for (int i = threadIdx.x; i < CH * CH; i += 256)
        Ss[i] = g_S[(long)bh * (CH * CH) + i];
    __syncthreads();

    int n = blockIdx.x * 512 + threadIdx.x;
    float acc0[CH], acc1[CH];
#pragma unroll
    for (int c = 0; c < CH; c++) { acc0[c] = 0.f; acc1[c] = 0.f; }

    for (int d = 0; d < CH; d++) {
        float v0 = vp[(d << 14) + n];
        float v1 = vp[(d << 14) + n + 256];
#pragma unroll
        for (int c = 0; c < CH; c++) {
            float s = Ss[c * CH + d];
            acc0[c] = fmaf(s, v0, acc0[c]);
            acc1[c] = fmaf(s, v1, acc1[c]);
        }
    }
#pragma unroll
    for (int c = 0; c < CH; c++) {
        op[(c << 14) + n] = acc0[c];
        op[(c << 14) + n + 256] = acc1[c];
    }
}

// ---------------- launch ----------------
extern "C" void kernel_launch(void* const* d_in, const int* in_sizes, int n_in,
                              void* d_out, int out_size)
{
    const float* x     = (const float*)d_in[0];
    const float* qkvw  = (const float*)d_in[1];
    const float* dww   = (const float*)d_in[2];
    const float* projw = (const float*)d_in[3];
    const float* temp  = (const float*)d_in[4];
    const float* uq    = (const float*)d_in[5];
    const float* ud    = (const float*)d_in[6];
    const float* up    = (const float*)d_in[7];
    float* out = (float*)d_out;

    float *t0, *t1, *ao;
    cudaGetSymbolAddress((void**)&t0, g_t0);
    cudaGetSymbolAddress((void**)&t1, g_t1);
    cudaGetSymbolAddress((void**)&ao, g_attn_out);

    // spectral sigmas + combined output scale (scales cancel everywhere else)
    sigma_kernel<<<3, 256>>>(qkvw, dww, projw, uq, ud, up);
    scale_kernel<<<1, 32>>>();

    // qkv 1x1 conv: GEMM [1152 x 384] x [384 x 16384] per batch (raw weights)
    sgemm128<<<dim3(HW / 128, C3 / 128, BATCH), 256>>>(
        qkvw, x, t0, C3, HW, DIM, (long)DIM * HW, (long)C3 * HW, 0);

    // 3x3 depthwise conv (raw weights)
    dwconv<<<dim3(16, C3, BATCH), 128>>>(t0, dww, t1);

    // q/k inverse L2 norms
    norm_kernel<<<BATCH * 2 * DIM, 256>>>(t1);

    // attention logits (partials), then scale/clamp/softmax
    attn_s<<<dim3(NCHUNKS, BATCH * HEADS), 256>>>(t1);
    softmax_kernel<<<BATCH * HEADS * CH, 64>>>(temp);

    // out = attn @ v
    attn_o<<<dim3(32, BATCH * HEADS), 256>>>(t1, ao);

    // proj 1x1 conv: GEMM [384 x 384] x [384 x 16384] per batch, with combined scale
    sgemm128<<<dim3(HW / 128, DIM / 128, BATCH), 256>>>(
        projw, ao, out, DIM, HW, DIM, (long)DIM * HW, (long)DIM * HW, 1);
}